// round 2
// baseline (speedup 1.0000x reference)
#include <cuda_runtime.h>
#include <cuda_bf16.h>
#include <math.h>

// Problem constants
#define NTOK   8192     // B*T = 4*2048
#define DDIM   1024
#define HDIM   2048
#define NEXP   8
#define TOPK   2
#define NSLOT  (NTOK*TOPK)          // 16384 gathered rows
#define TILE_M 128
#define MCAP   (NSLOT + NEXP*TILE_M) // 17408 padded capacity
#define MTILES (MCAP/TILE_M)         // 136
#define LN_EPS 1e-5f

// ---------------- device scratch (static: no allocations allowed) ----------
__device__ float g_Xg[(size_t)MCAP * DDIM];   // gathered tokens        ~71 MB
__device__ float g_Hg[(size_t)MCAP * HDIM];   // gelu(Xg@W1+b1)        ~143 MB
__device__ float g_Yg[(size_t)MCAP * DDIM];   // Hg@W2+b2               ~71 MB
__device__ int   g_count[NEXP];
__device__ int   g_cursor[NEXP];
__device__ int   g_off[NEXP + 1];
__device__ int   g_tileExpert[MTILES];
__device__ int   g_slotE[NSLOT];
__device__ float g_slotW[NSLOT];
__device__ int   g_slotPos[NSLOT];
__device__ float g_imp[NEXP];
__device__ float g_ent;

// ---------------- init: zero per-launch accumulators -----------------------
__global__ void init_kernel() {
    int t = threadIdx.x;
    if (t < NEXP) { g_count[t] = 0; g_cursor[t] = 0; g_imp[t] = 0.f; }
    if (t == 0)   g_ent = 0.f;
}

// ---------------- router: fp32 logits, top-2, softmax, aux stats -----------
__global__ void router_kernel(const float* __restrict__ x,
                              const float* __restrict__ gW,
                              const float* __restrict__ gb) {
    int n    = blockIdx.x;
    int w    = threadIdx.x >> 5;     // warp = expert
    int lane = threadIdx.x & 31;
    const float* xr = x + (size_t)n * DDIM;

    float s = 0.f;
    #pragma unroll 4
    for (int d = lane; d < DDIM; d += 32)
        s += xr[d] * gW[d * NEXP + w];
    #pragma unroll
    for (int o = 16; o; o >>= 1) s += __shfl_xor_sync(0xffffffffu, s, o);

    __shared__ float lg[NEXP];
    if (lane == 0) lg[w] = s + gb[w];
    __syncthreads();

    if (threadIdx.x == 0) {
        float l[NEXP];
        #pragma unroll
        for (int e = 0; e < NEXP; e++) l[e] = lg[e];
        // top-2 (first occurrence wins, matching jax.lax.top_k tie rule)
        int i1 = 0;
        #pragma unroll
        for (int e = 1; e < NEXP; e++) if (l[e] > l[i1]) i1 = e;
        int i2 = -1;
        #pragma unroll
        for (int e = 0; e < NEXP; e++)
            if (e != i1 && (i2 < 0 || l[e] > l[i2])) i2 = e;
        float v1 = l[i1], v2 = l[i2];
        float e2 = expf(v2 - v1);
        float p1 = 1.f / (1.f + e2);
        float p2 = e2 * p1;
        g_slotE[2*n]   = i1;  g_slotE[2*n+1]   = i2;
        g_slotW[2*n]   = p1;  g_slotW[2*n+1]   = p2;
        atomicAdd(&g_count[i1], 1);
        atomicAdd(&g_count[i2], 1);
        // full softmax for importance / entropy
        float p[NEXP], sum = 0.f;
        #pragma unroll
        for (int e = 0; e < NEXP; e++) { p[e] = expf(l[e] - v1); sum += p[e]; }
        float inv = 1.f / sum, ent = 0.f;
        #pragma unroll
        for (int e = 0; e < NEXP; e++) {
            p[e] *= inv;
            atomicAdd(&g_imp[e], p[e]);
            ent -= p[e] * logf(p[e] + 1e-8f);
        }
        atomicAdd(&g_ent, ent);
    }
}

// ---------------- offsets: padded segments + tile->expert map --------------
__global__ void offsets_kernel() {
    if (threadIdx.x == 0 && blockIdx.x == 0) {
        int off = 0;
        for (int e = 0; e < NEXP; e++) {
            g_off[e] = off;
            int pc = (g_count[e] + TILE_M - 1) & ~(TILE_M - 1);
            int t0 = off >> 7, t1 = (off + pc) >> 7;
            for (int t = t0; t < t1; t++) g_tileExpert[t] = e;
            off += pc;
        }
        g_off[NEXP] = off;
        for (int t = off >> 7; t < MTILES; t++) g_tileExpert[t] = -1;
    }
}

// ---------------- gather tokens into expert segments -----------------------
__global__ void gather_kernel(const float* __restrict__ x) {
    int n = blockIdx.x;
    __shared__ int pos[2];
    if (threadIdx.x == 0) {
        int e0 = g_slotE[2*n], e1 = g_slotE[2*n+1];
        pos[0] = g_off[e0] + atomicAdd(&g_cursor[e0], 1);
        pos[1] = g_off[e1] + atomicAdd(&g_cursor[e1], 1);
        g_slotPos[2*n] = pos[0]; g_slotPos[2*n+1] = pos[1];
    }
    __syncthreads();
    const float4* xr = (const float4*)(x + (size_t)n * DDIM);
    float4* d0 = (float4*)(g_Xg + (size_t)pos[0] * DDIM);
    float4* d1 = (float4*)(g_Xg + (size_t)pos[1] * DDIM);
    int i = threadIdx.x;                  // 256 threads, 256 float4 per row
    float4 v = xr[i];
    d0[i] = v; d1[i] = v;
}

// ---------------- zero padded rows (avoid stale data in compute tiles) -----
__global__ void padzero_kernel() {
    int b = blockIdx.x;             // 0..NEXP*TILE_M-1
    int e = b >> 7, r = b & 127;
    int row = g_off[e] + g_count[e] + r;
    if (row < g_off[e + 1]) {
        float4* d = (float4*)(g_Xg + (size_t)row * DDIM);
        d[threadIdx.x] = make_float4(0.f, 0.f, 0.f, 0.f);
    }
}

// ---------------- per-expert tiled sgemm (128x128x16, 8x8 per thread) ------
// STAGE 0: g_Xg [M,1024] @ W1[e] [1024,2048] -> gelu -> g_Hg
// STAGE 1: g_Hg [M,2048] @ W2[e] [2048,1024] ->          g_Yg
// NOTE: scratch buffers are referenced as device symbols INSIDE device code.
// Never pass __device__ globals as kernel arguments from host (R1 bug: host
// shadow addresses are ATS-valid on GB300 and silently read host memory).
__device__ __forceinline__ float gelu_exact(float v) {
    return 0.5f * v * (1.f + erff(v * 0.70710678118654752f));
}

template <int STAGE>
__global__ __launch_bounds__(256) void expert_gemm(
    const float* __restrict__ W, const float* __restrict__ bias)
{
    constexpr int K = (STAGE == 0) ? DDIM : HDIM;
    constexpr int N = (STAGE == 0) ? HDIM : DDIM;
    const float* A = (STAGE == 0) ? g_Xg : g_Hg;
    float*       C = (STAGE == 0) ? g_Hg : g_Yg;

    int e = g_tileExpert[blockIdx.x];
    if (e < 0) return;
    const float* B  = W    + (size_t)e * K * N;
    const float* bv = bias + (size_t)e * N;
    int m0 = blockIdx.x * TILE_M;
    int n0 = blockIdx.y * 128;

    __shared__ float As[16][128];
    __shared__ float Bs[16][128];

    float acc[8][8];
    #pragma unroll
    for (int i = 0; i < 8; i++)
        #pragma unroll
        for (int j = 0; j < 8; j++) acc[i][j] = 0.f;

    int tid  = threadIdx.x;
    int arow = tid >> 1, acol = (tid & 1) * 8;     // A: 128 rows x 16 cols
    int brow = tid >> 4, bcol = (tid & 15) * 8;    // B: 16 rows x 128 cols
    int tx = tid & 15, ty = tid >> 4;

    const float* Aptr = A + (size_t)(m0 + arow) * K + acol;
    const float* Bptr = B + (size_t)brow * N + n0 + bcol;

    for (int k0 = 0; k0 < K; k0 += 16) {
        float4 av0 = *(const float4*)(Aptr + k0);
        float4 av1 = *(const float4*)(Aptr + k0 + 4);
        float4 bb0 = *(const float4*)(Bptr + (size_t)k0 * N);
        float4 bb1 = *(const float4*)(Bptr + (size_t)k0 * N + 4);
        As[acol + 0][arow] = av0.x;
        As[acol + 1][arow] = av0.y;
        As[acol + 2][arow] = av0.z;
        As[acol + 3][arow] = av0.w;
        As[acol + 4][arow] = av1.x;
        As[acol + 5][arow] = av1.y;
        As[acol + 6][arow] = av1.z;
        As[acol + 7][arow] = av1.w;
        *(float4*)&Bs[brow][bcol]     = bb0;
        *(float4*)&Bs[brow][bcol + 4] = bb1;
        __syncthreads();
        #pragma unroll
        for (int kk = 0; kk < 16; kk++) {
            float a[8], b[8];
            *(float4*)(a)     = *(const float4*)&As[kk][ty * 4];
            *(float4*)(a + 4) = *(const float4*)&As[kk][64 + ty * 4];
            *(float4*)(b)     = *(const float4*)&Bs[kk][tx * 4];
            *(float4*)(b + 4) = *(const float4*)&Bs[kk][64 + tx * 4];
            #pragma unroll
            for (int i = 0; i < 8; i++)
                #pragma unroll
                for (int j = 0; j < 8; j++)
                    acc[i][j] += a[i] * b[j];
        }
        __syncthreads();
    }

    float4 bias0 = *(const float4*)(bv + n0 + tx * 4);
    float4 bias1 = *(const float4*)(bv + n0 + 64 + tx * 4);
    float bcols[8] = {bias0.x, bias0.y, bias0.z, bias0.w,
                      bias1.x, bias1.y, bias1.z, bias1.w};

    #pragma unroll
    for (int i = 0; i < 8; i++) {
        int mloc = (i < 4) ? (ty * 4 + i) : (64 + ty * 4 + (i - 4));
        float* crow = C + (size_t)(m0 + mloc) * N + n0;
        float v[8];
        #pragma unroll
        for (int j = 0; j < 8; j++) {
            float t = acc[i][j] + bcols[j];
            v[j] = (STAGE == 0) ? gelu_exact(t) : t;
        }
        *(float4*)(crow + tx * 4)      = make_float4(v[0], v[1], v[2], v[3]);
        *(float4*)(crow + 64 + tx * 4) = make_float4(v[4], v[5], v[6], v[7]);
    }
}

// ---------------- combine: gate-weighted sum + residual + layernorm --------
__global__ __launch_bounds__(256) void combine_ln(
    const float* __restrict__ x,
    const float* __restrict__ gamma,
    const float* __restrict__ beta,
    float* __restrict__ out)
{
    int n   = blockIdx.x;
    int tid = threadIdx.x;   // 256 threads, one float4 each (1024 elems)
    int   p0 = g_slotPos[2*n], p1 = g_slotPos[2*n+1];
    float w0 = g_slotW[2*n],   w1 = g_slotW[2*n+1];

    const float4* xr = (const float4*)(x    + (size_t)n  * DDIM);
    const float4* y0 = (const float4*)(g_Yg + (size_t)p0 * DDIM);
    const float4* y1 = (const float4*)(g_Yg + (size_t)p1 * DDIM);

    float4 a = y0[tid], b = y1[tid], xv = xr[tid];
    float4 z;
    z.x = w0 * a.x + w1 * b.x + xv.x;
    z.y = w0 * a.y + w1 * b.y + xv.y;
    z.z = w0 * a.z + w1 * b.z + xv.z;
    z.w = w0 * a.w + w1 * b.w + xv.w;

    float s  = z.x + z.y + z.z + z.w;
    float sq = z.x * z.x + z.y * z.y + z.z * z.z + z.w * z.w;
    #pragma unroll
    for (int o = 16; o; o >>= 1) {
        s  += __shfl_xor_sync(0xffffffffu, s,  o);
        sq += __shfl_xor_sync(0xffffffffu, sq, o);
    }
    __shared__ float ws[8], wq[8];
    int wid = tid >> 5, lane = tid & 31;
    if (lane == 0) { ws[wid] = s; wq[wid] = sq; }
    __syncthreads();
    __shared__ float mu_s, inv_s;
    if (tid == 0) {
        float ts = 0.f, tq = 0.f;
        #pragma unroll
        for (int i = 0; i < 8; i++) { ts += ws[i]; tq += wq[i]; }
        float mu  = ts * (1.f / DDIM);
        float var = tq * (1.f / DDIM) - mu * mu;
        mu_s  = mu;
        inv_s = rsqrtf(var + LN_EPS);
    }
    __syncthreads();
    float mu = mu_s, inv = inv_s;

    float4 g = ((const float4*)gamma)[tid];
    float4 be = ((const float4*)beta)[tid];
    float4 o4;
    o4.x = (z.x - mu) * inv * g.x + be.x;
    o4.y = (z.y - mu) * inv * g.y + be.y;
    o4.z = (z.z - mu) * inv * g.z + be.z;
    o4.w = (z.w - mu) * inv * g.w + be.w;
    ((float4*)out)[(size_t)n * (DDIM / 4) + tid] = o4;
}

// ---------------- finalize aux outputs -------------------------------------
__global__ void finalize_kernel(float* __restrict__ out, int out_size) {
    if (threadIdx.x == 0 && blockIdx.x == 0) {
        const size_t ND = (size_t)NTOK * DDIM;
        float invN = 1.f / (float)NTOK;
        float loadv[NEXP], impv[NEXP];
        float bal = 0.f, ue = 0.f;
        for (int e = 0; e < NEXP; e++) {
            loadv[e] = (float)g_count[e] * invN;
            impv[e]  = g_imp[e] * invN;
            bal += impv[e] * loadv[e];
            ue  -= loadv[e] * logf(loadv[e] + 1e-8f);
        }
        float vals[3 + 2 * NEXP];
        vals[0] = (float)NEXP * bal;      // balance_loss
        vals[1] = g_ent * invN;           // entropy
        vals[2] = ue;                     // utilization_entropy
        for (int e = 0; e < NEXP; e++) { vals[3 + e] = loadv[e]; vals[11 + e] = impv[e]; }
        for (int i = 0; i < 3 + 2 * NEXP; i++) {
            size_t idx = ND + (size_t)i;
            if (idx < (size_t)out_size) out[idx] = vals[i];
        }
    }
}

// ---------------- launcher --------------------------------------------------
extern "C" void kernel_launch(void* const* d_in, const int* in_sizes, int n_in,
                              void* d_out, int out_size) {
    const float* x     = (const float*)d_in[0];
    const float* gateW = (const float*)d_in[1];
    const float* gateB = (const float*)d_in[2];
    const float* W1    = (const float*)d_in[3];
    const float* b1    = (const float*)d_in[4];
    const float* W2    = (const float*)d_in[5];
    const float* b2    = (const float*)d_in[6];
    const float* lngam = (const float*)d_in[7];
    const float* lnbet = (const float*)d_in[8];
    float* out = (float*)d_out;

    init_kernel<<<1, 32>>>();
    router_kernel<<<NTOK, 256>>>(x, gateW, gateB);
    offsets_kernel<<<1, 32>>>();
    gather_kernel<<<NTOK, 256>>>(x);
    padzero_kernel<<<NEXP * TILE_M, 256>>>();
    expert_gemm<0><<<dim3(MTILES, HDIM / 128), 256>>>(W1, b1);
    expert_gemm<1><<<dim3(MTILES, DDIM / 128), 256>>>(W2, b2);
    combine_ln<<<NTOK, 256>>>(x, lngam, lnbet, out);
    finalize_kernel<<<1, 32>>>(out, out_size);
}

// round 7
// speedup vs baseline: 3.9782x; 3.9782x over previous
#include <cuda_runtime.h>
#include <cuda_bf16.h>
#include <math.h>
#include <stdint.h>

// Problem constants
#define NTOK   8192     // B*T
#define DDIM   1024
#define HDIM   2048
#define NEXP   8
#define TOPK   2
#define NSLOT  (NTOK*TOPK)
#define TILE_M 128
#define MCAP   (NSLOT + NEXP*TILE_M)  // 17408
#define MTILES (MCAP/TILE_M)          // 136
#define LN_EPS 1e-5f

// ---------------- device scratch (no allocations allowed) ------------------
__device__ __nv_bfloat16 g_Xg [(size_t)MCAP * DDIM];        // gathered tokens (bf16)
__device__ __nv_bfloat16 g_Hbf[(size_t)MCAP * HDIM];        // gelu(X@W1+b1) (bf16)
__device__ float         g_Yg [(size_t)MCAP * DDIM];        // H@W2+b2 (fp32)
__device__ __nv_bfloat16 g_W1t[(size_t)NEXP * HDIM * DDIM]; // W1^T bf16 [E][N=H][K=D]
__device__ __nv_bfloat16 g_W2t[(size_t)NEXP * DDIM * HDIM]; // W2^T bf16 [E][N=D][K=H]
__device__ int   g_count[NEXP];
__device__ int   g_cursor[NEXP];
__device__ int   g_off[NEXP + 1];
__device__ int   g_tileExpert[MTILES];
__device__ int   g_slotE[NSLOT];
__device__ float g_slotW[NSLOT];
__device__ int   g_slotPos[NSLOT];
__device__ float g_imp[NEXP];
__device__ float g_ent;

// ---------------- helpers ---------------------------------------------------
__device__ __forceinline__ uint32_t smem_to_u32(const void* p) {
    uint32_t a;
    asm("{ .reg .u64 t; cvta.to.shared.u64 t, %1; cvt.u32.u64 %0, t; }"
        : "=r"(a) : "l"(p));
    return a;
}
__device__ __forceinline__ void cp16(uint32_t s, const void* g) {
    asm volatile("cp.async.cg.shared.global [%0], [%1], 16;" :: "r"(s), "l"(g));
}
#define CP_COMMIT()  asm volatile("cp.async.commit_group;" ::: "memory")
#define CP_WAIT(n)   asm volatile("cp.async.wait_group %0;" :: "n"(n) : "memory")

__device__ __forceinline__ void ldsm4(uint32_t& r0, uint32_t& r1, uint32_t& r2,
                                      uint32_t& r3, uint32_t addr) {
    asm volatile("ldmatrix.sync.aligned.m8n8.x4.shared.b16 {%0,%1,%2,%3}, [%4];"
                 : "=r"(r0), "=r"(r1), "=r"(r2), "=r"(r3) : "r"(addr));
}
__device__ __forceinline__ void mma16816(float* c, const uint32_t* a, const uint32_t* b) {
    asm volatile(
        "mma.sync.aligned.m16n8k16.row.col.f32.bf16.bf16.f32 "
        "{%0,%1,%2,%3}, {%4,%5,%6,%7}, {%8,%9}, {%0,%1,%2,%3};"
        : "+f"(c[0]), "+f"(c[1]), "+f"(c[2]), "+f"(c[3])
        : "r"(a[0]), "r"(a[1]), "r"(a[2]), "r"(a[3]), "r"(b[0]), "r"(b[1]));
}
__device__ __forceinline__ uint32_t pack_bf16x2(float lo, float hi) {
    __nv_bfloat162 t = __floats2bfloat162_rn(lo, hi);
    return *reinterpret_cast<uint32_t*>(&t);
}
__device__ __forceinline__ float gelu_exact(float v) {
    return 0.5f * v * (1.f + erff(v * 0.70710678118654752f));
}

// ---------------- init ------------------------------------------------------
__global__ void init_kernel() {
    int t = threadIdx.x;
    if (t < NEXP) { g_count[t] = 0; g_cursor[t] = 0; g_imp[t] = 0.f; }
    if (t == 0)   g_ent = 0.f;
}

// ---------------- router (fp32) ---------------------------------------------
__global__ void router_kernel(const float* __restrict__ x,
                              const float* __restrict__ gW,
                              const float* __restrict__ gb) {
    int n    = blockIdx.x;
    int w    = threadIdx.x >> 5;
    int lane = threadIdx.x & 31;
    const float* xr = x + (size_t)n * DDIM;

    float s = 0.f;
    #pragma unroll 4
    for (int d = lane; d < DDIM; d += 32)
        s += xr[d] * gW[d * NEXP + w];
    #pragma unroll
    for (int o = 16; o; o >>= 1) s += __shfl_xor_sync(0xffffffffu, s, o);

    __shared__ float lg[NEXP];
    if (lane == 0) lg[w] = s + gb[w];
    __syncthreads();

    if (threadIdx.x == 0) {
        float l[NEXP];
        #pragma unroll
        for (int e = 0; e < NEXP; e++) l[e] = lg[e];
        int i1 = 0;
        #pragma unroll
        for (int e = 1; e < NEXP; e++) if (l[e] > l[i1]) i1 = e;
        int i2 = -1;
        #pragma unroll
        for (int e = 0; e < NEXP; e++)
            if (e != i1 && (i2 < 0 || l[e] > l[i2])) i2 = e;
        float v1 = l[i1], v2 = l[i2];
        float e2 = expf(v2 - v1);
        float p1 = 1.f / (1.f + e2);
        float p2 = e2 * p1;
        g_slotE[2*n] = i1;  g_slotE[2*n+1] = i2;
        g_slotW[2*n] = p1;  g_slotW[2*n+1] = p2;
        atomicAdd(&g_count[i1], 1);
        atomicAdd(&g_count[i2], 1);
        float p[NEXP], sum = 0.f;
        #pragma unroll
        for (int e = 0; e < NEXP; e++) { p[e] = expf(l[e] - v1); sum += p[e]; }
        float inv = 1.f / sum, ent = 0.f;
        #pragma unroll
        for (int e = 0; e < NEXP; e++) {
            p[e] *= inv;
            atomicAdd(&g_imp[e], p[e]);
            ent -= p[e] * logf(p[e] + 1e-8f);
        }
        atomicAdd(&g_ent, ent);
    }
}

// ---------------- offsets ---------------------------------------------------
__global__ void offsets_kernel() {
    if (threadIdx.x == 0 && blockIdx.x == 0) {
        int off = 0;
        for (int e = 0; e < NEXP; e++) {
            g_off[e] = off;
            int pc = (g_count[e] + TILE_M - 1) & ~(TILE_M - 1);
            int t0 = off >> 7, t1 = (off + pc) >> 7;
            for (int t = t0; t < t1; t++) g_tileExpert[t] = e;
            off += pc;
        }
        g_off[NEXP] = off;
        for (int t = off >> 7; t < MTILES; t++) g_tileExpert[t] = -1;
    }
}

// ---------------- gather: fp32 -> bf16 rows ---------------------------------
__global__ void gather_kernel(const float* __restrict__ x) {
    int n = blockIdx.x;
    __shared__ int pos[2];
    if (threadIdx.x == 0) {
        int e0 = g_slotE[2*n], e1 = g_slotE[2*n+1];
        pos[0] = g_off[e0] + atomicAdd(&g_cursor[e0], 1);
        pos[1] = g_off[e1] + atomicAdd(&g_cursor[e1], 1);
        g_slotPos[2*n] = pos[0]; g_slotPos[2*n+1] = pos[1];
    }
    __syncthreads();
    const float4* xr = (const float4*)(x + (size_t)n * DDIM);
    int i = threadIdx.x;
    float4 v = xr[i];
    uint2 u;
    u.x = pack_bf16x2(v.x, v.y);
    u.y = pack_bf16x2(v.z, v.w);
    ((uint2*)(g_Xg + (size_t)pos[0] * DDIM))[i] = u;
    ((uint2*)(g_Xg + (size_t)pos[1] * DDIM))[i] = u;
}

// ---------------- zero padded rows ------------------------------------------
__global__ void padzero_kernel() {
    int b = blockIdx.x;
    int e = b >> 7, r = b & 127;
    int row = g_off[e] + g_count[e] + r;
    if (row < g_off[e + 1]) {
        uint2 z = make_uint2(0u, 0u);
        ((uint2*)(g_Xg + (size_t)row * DDIM))[threadIdx.x] = z;
    }
}

// ---------------- weight transpose + bf16: W[E][K][N] -> Wt[E][N][K] --------
template <int STAGE>
__global__ void transpose_w(const float* __restrict__ W) {
    constexpr int K = (STAGE == 0) ? DDIM : HDIM;
    constexpr int N = (STAGE == 0) ? HDIM : DDIM;
    __nv_bfloat16* Wt = (STAGE == 0) ? g_W1t : g_W2t;
    int e   = blockIdx.z;
    int in0 = blockIdx.x * 32, ik0 = blockIdx.y * 32;
    __shared__ float t[32][33];
    const float* Wsrc = W + (size_t)e * K * N;
    int tx = threadIdx.x, ty = threadIdx.y;   // 32 x 8
    #pragma unroll
    for (int j = 0; j < 4; j++) {
        int k = ik0 + ty + j * 8;
        t[ty + j * 8][tx] = Wsrc[(size_t)k * N + in0 + tx];
    }
    __syncthreads();
    #pragma unroll
    for (int j = 0; j < 4; j++) {
        int n = in0 + ty + j * 8;
        Wt[((size_t)e * N + n) * K + ik0 + tx] = __float2bfloat16(t[tx][ty + j * 8]);
    }
}

// ---------------- mma.sync expert GEMM (128x128 tile, bf16 HMMA) ------------
// STAGE 0: g_Xg [M,1024] @ W1t -> bias+gelu -> g_Hbf (bf16)
// STAGE 1: g_Hbf [M,2048] @ W2t -> bias      -> g_Yg  (fp32)
// 8 warps (2 M x 4 N), warp tile 64x32, K-chunk 32, double-buffered cp.async.
// Smem rows padded to 80B (20 banks): ldmatrix 8-row loads conflict-free.
#define ROWB    80
#define TILEB   (128 * ROWB)      // 10240 per operand
#define STAGEB  (2 * TILEB)       // A+B per stage

template <int STAGE>
__global__ __launch_bounds__(256) void expert_gemm_mma(const float* __restrict__ bias)
{
    constexpr int K  = (STAGE == 0) ? DDIM : HDIM;
    constexpr int N  = (STAGE == 0) ? HDIM : DDIM;
    constexpr int NC = K / 32;
    const __nv_bfloat16* A  = (STAGE == 0) ? g_Xg  : g_Hbf;
    const __nv_bfloat16* Wt = (STAGE == 0) ? g_W1t : g_W2t;

    int e = g_tileExpert[blockIdx.x];
    if (e < 0) return;
    int m0 = blockIdx.x * TILE_M;
    int n0 = blockIdx.y * 128;

    __shared__ __align__(128) char sm[2 * STAGEB];
    uint32_t sbase = smem_to_u32(sm);

    int tid  = threadIdx.x;
    int wid  = tid >> 5, lane = tid & 31;
    int m_w  = (wid & 1) * 64;          // warp M offset in tile
    int n_w  = (wid >> 1) * 32;         // warp N offset in tile

    const __nv_bfloat16* Abase = A  + (size_t)m0 * K;
    const __nv_bfloat16* Bbase = Wt + ((size_t)e * N + n0) * K;

    // per-thread copy assignment: row = tid>>1, two 16B quarters
    int crow = tid >> 1;
    int cqb  = (tid & 1) * 32;          // byte offset within 64B of k-chunk

    auto copy_chunk = [&](int kc, int st) {
        const char* gA = (const char*)(Abase + (size_t)crow * K + kc * 32) + cqb;
        const char* gB = (const char*)(Bbase + (size_t)crow * K + kc * 32) + cqb;
        uint32_t sA = sbase + st * STAGEB + crow * ROWB + cqb;
        uint32_t sB = sA + TILEB;
        cp16(sA,      gA);
        cp16(sA + 16, gA + 16);
        cp16(sB,      gB);
        cp16(sB + 16, gB + 16);
    };

    float acc[4][4][4];
    #pragma unroll
    for (int i = 0; i < 4; i++)
        #pragma unroll
        for (int j = 0; j < 4; j++)
            #pragma unroll
            for (int q = 0; q < 4; q++) acc[i][j][q] = 0.f;

    // ldmatrix lane address components
    int lr = lane & 7, lg = lane >> 3;
    uint32_t aoff = (uint32_t)(m_w + lr + (lg & 1) * 8) * ROWB + (lg >> 1) * 16;
    uint32_t boff = (uint32_t)(n_w + (lg >> 1) * 8 + lr) * ROWB + (lg & 1) * 16;

    copy_chunk(0, 0);
    CP_COMMIT();

    for (int kc = 0; kc < NC; kc++) {
        int st = kc & 1;
        if (kc + 1 < NC) {
            copy_chunk(kc + 1, st ^ 1);
            CP_COMMIT();
            CP_WAIT(1);
        } else {
            CP_WAIT(0);
        }
        __syncthreads();

        uint32_t sA = sbase + st * STAGEB;
        uint32_t sB = sA + TILEB;
        #pragma unroll
        for (int ks = 0; ks < 2; ks++) {
            uint32_t a[4][4], b[4][2];
            #pragma unroll
            for (int f = 0; f < 4; f++)
                ldsm4(a[f][0], a[f][1], a[f][2], a[f][3],
                      sA + aoff + f * (16 * ROWB) + ks * 32);
            #pragma unroll
            for (int fb = 0; fb < 2; fb++)
                ldsm4(b[2*fb][0], b[2*fb][1], b[2*fb+1][0], b[2*fb+1][1],
                      sB + boff + fb * (16 * ROWB) + ks * 32);
            #pragma unroll
            for (int mf = 0; mf < 4; mf++)
                #pragma unroll
                for (int nf = 0; nf < 4; nf++)
                    mma16816(acc[mf][nf], a[mf], b[nf]);
        }
        __syncthreads();
    }

    // ---- epilogue: bias (+GELU), direct global stores ----
    float bv[4][2];
    #pragma unroll
    for (int nf = 0; nf < 4; nf++) {
        int c = n0 + n_w + nf * 8 + (lane & 3) * 2;
        bv[nf][0] = bias[(size_t)e * N + c];
        bv[nf][1] = bias[(size_t)e * N + c + 1];
    }
    #pragma unroll
    for (int mf = 0; mf < 4; mf++) {
        #pragma unroll
        for (int sub = 0; sub < 2; sub++) {
            int row = m0 + m_w + mf * 16 + (lane >> 2) + sub * 8;
            #pragma unroll
            for (int nf = 0; nf < 4; nf++) {
                int col = n0 + n_w + nf * 8 + (lane & 3) * 2;
                float v0 = acc[mf][nf][sub * 2]     + bv[nf][0];
                float v1 = acc[mf][nf][sub * 2 + 1] + bv[nf][1];
                if (STAGE == 0) {
                    *(uint32_t*)(g_Hbf + (size_t)row * N + col) =
                        pack_bf16x2(gelu_exact(v0), gelu_exact(v1));
                } else {
                    *(float2*)(g_Yg + (size_t)row * N + col) = make_float2(v0, v1);
                }
            }
        }
    }
}

// ---------------- combine: gates + residual + layernorm (fp32) --------------
__global__ __launch_bounds__(256) void combine_ln(
    const float* __restrict__ x,
    const float* __restrict__ gamma,
    const float* __restrict__ beta,
    float* __restrict__ out)
{
    int n   = blockIdx.x;
    int tid = threadIdx.x;
    int   p0 = g_slotPos[2*n], p1 = g_slotPos[2*n+1];
    float w0 = g_slotW[2*n],   w1 = g_slotW[2*n+1];

    const float4* xr = (const float4*)(x    + (size_t)n  * DDIM);
    const float4* y0 = (const float4*)(g_Yg + (size_t)p0 * DDIM);
    const float4* y1 = (const float4*)(g_Yg + (size_t)p1 * DDIM);

    float4 a = y0[tid], b = y1[tid], xv = xr[tid];
    float4 z;
    z.x = w0 * a.x + w1 * b.x + xv.x;
    z.y = w0 * a.y + w1 * b.y + xv.y;
    z.z = w0 * a.z + w1 * b.z + xv.z;
    z.w = w0 * a.w + w1 * b.w + xv.w;

    float s  = z.x + z.y + z.z + z.w;
    float sq = z.x * z.x + z.y * z.y + z.z * z.z + z.w * z.w;
    #pragma unroll
    for (int o = 16; o; o >>= 1) {
        s  += __shfl_xor_sync(0xffffffffu, s,  o);
        sq += __shfl_xor_sync(0xffffffffu, sq, o);
    }
    __shared__ float ws[8], wq[8];
    int wid = tid >> 5, lane = tid & 31;
    if (lane == 0) { ws[wid] = s; wq[wid] = sq; }
    __syncthreads();
    __shared__ float mu_s, inv_s;
    if (tid == 0) {
        float ts = 0.f, tq = 0.f;
        #pragma unroll
        for (int i = 0; i < 8; i++) { ts += ws[i]; tq += wq[i]; }
        float mu  = ts * (1.f / DDIM);
        float var = tq * (1.f / DDIM) - mu * mu;
        mu_s  = mu;
        inv_s = rsqrtf(var + LN_EPS);
    }
    __syncthreads();
    float mu = mu_s, inv = inv_s;

    float4 g  = ((const float4*)gamma)[tid];
    float4 be = ((const float4*)beta)[tid];
    float4 o4;
    o4.x = (z.x - mu) * inv * g.x + be.x;
    o4.y = (z.y - mu) * inv * g.y + be.y;
    o4.z = (z.z - mu) * inv * g.z + be.z;
    o4.w = (z.w - mu) * inv * g.w + be.w;
    ((float4*)out)[(size_t)n * (DDIM / 4) + tid] = o4;
}

// ---------------- finalize aux outputs --------------------------------------
__global__ void finalize_kernel(float* __restrict__ out, int out_size) {
    if (threadIdx.x == 0 && blockIdx.x == 0) {
        const size_t ND = (size_t)NTOK * DDIM;
        float invN = 1.f / (float)NTOK;
        float loadv[NEXP], impv[NEXP];
        float bal = 0.f, ue = 0.f;
        for (int e = 0; e < NEXP; e++) {
            loadv[e] = (float)g_count[e] * invN;
            impv[e]  = g_imp[e] * invN;
            bal += impv[e] * loadv[e];
            ue  -= loadv[e] * logf(loadv[e] + 1e-8f);
        }
        float vals[3 + 2 * NEXP];
        vals[0] = (float)NEXP * bal;
        vals[1] = g_ent * invN;
        vals[2] = ue;
        for (int e = 0; e < NEXP; e++) { vals[3 + e] = loadv[e]; vals[11 + e] = impv[e]; }
        for (int i = 0; i < 3 + 2 * NEXP; i++) {
            size_t idx = ND + (size_t)i;
            if (idx < (size_t)out_size) out[idx] = vals[i];
        }
    }
}

// ---------------- launcher --------------------------------------------------
extern "C" void kernel_launch(void* const* d_in, const int* in_sizes, int n_in,
                              void* d_out, int out_size) {
    const float* x     = (const float*)d_in[0];
    const float* gateW = (const float*)d_in[1];
    const float* gateB = (const float*)d_in[2];
    const float* W1    = (const float*)d_in[3];
    const float* b1    = (const float*)d_in[4];
    const float* W2    = (const float*)d_in[5];
    const float* b2    = (const float*)d_in[6];
    const float* lngam = (const float*)d_in[7];
    const float* lnbet = (const float*)d_in[8];
    float* out = (float*)d_out;

    init_kernel<<<1, 32>>>();
    router_kernel<<<NTOK, 256>>>(x, gateW, gateB);
    offsets_kernel<<<1, 32>>>();
    gather_kernel<<<NTOK, 256>>>(x);
    padzero_kernel<<<NEXP * TILE_M, 256>>>();
    transpose_w<0><<<dim3(HDIM / 32, DDIM / 32, NEXP), dim3(32, 8)>>>(W1);
    transpose_w<1><<<dim3(DDIM / 32, HDIM / 32, NEXP), dim3(32, 8)>>>(W2);
    expert_gemm_mma<0><<<dim3(MTILES, HDIM / 128), 256>>>(b1);
    expert_gemm_mma<1><<<dim3(MTILES, DDIM / 128), 256>>>(b2);
    combine_ln<<<NTOK, 256>>>(x, lngam, lnbet, out);
    finalize_kernel<<<1, 32>>>(out, out_size);
}

// round 9
// speedup vs baseline: 4.3192x; 1.0857x over previous
#include <cuda_runtime.h>
#include <cuda_bf16.h>
#include <math.h>
#include <stdint.h>

// Problem constants
#define NTOK   8192     // B*T
#define DDIM   1024
#define HDIM   2048
#define NEXP   8
#define TOPK   2
#define NSLOT  (NTOK*TOPK)
#define TILE_M 128
#define MCAP   (NSLOT + NEXP*TILE_M)  // 17408
#define MTILES (MCAP/TILE_M)          // 136
#define LN_EPS 1e-5f

// ---------------- device scratch (no allocations allowed) ------------------
__device__ __nv_bfloat16 g_Xg [(size_t)MCAP * DDIM];        // gathered tokens (bf16)
__device__ __nv_bfloat16 g_Hbf[(size_t)MCAP * HDIM];        // gelu(X@W1+b1) (bf16)
__device__ float         g_Yg [(size_t)MCAP * DDIM];        // H@W2+b2 (fp32)
__device__ __nv_bfloat16 g_W1c[(size_t)NEXP * DDIM * HDIM]; // W1 bf16 [E][K=D][N=H]
__device__ __nv_bfloat16 g_W2c[(size_t)NEXP * HDIM * DDIM]; // W2 bf16 [E][K=H][N=D]
__device__ int   g_count[NEXP];
__device__ int   g_cursor[NEXP];
__device__ int   g_off[NEXP + 1];
__device__ int   g_tileExpert[MTILES];
__device__ int   g_slotE[NSLOT];
__device__ float g_slotW[NSLOT];
__device__ int   g_slotPos[NSLOT];
__device__ float g_imp[NEXP];
__device__ float g_ent;

// ---------------- helpers ---------------------------------------------------
__device__ __forceinline__ uint32_t smem_to_u32(const void* p) {
    uint32_t a;
    asm("{ .reg .u64 t; cvta.to.shared.u64 t, %1; cvt.u32.u64 %0, t; }"
        : "=r"(a) : "l"(p));
    return a;
}
__device__ __forceinline__ void cp16(uint32_t s, const void* g) {
    asm volatile("cp.async.cg.shared.global [%0], [%1], 16;" :: "r"(s), "l"(g));
}
#define CP_COMMIT()  asm volatile("cp.async.commit_group;" ::: "memory")
#define CP_WAIT(n)   asm volatile("cp.async.wait_group %0;" :: "n"(n) : "memory")

__device__ __forceinline__ void ldsm4(uint32_t& r0, uint32_t& r1, uint32_t& r2,
                                      uint32_t& r3, uint32_t addr) {
    asm volatile("ldmatrix.sync.aligned.m8n8.x4.shared.b16 {%0,%1,%2,%3}, [%4];"
                 : "=r"(r0), "=r"(r1), "=r"(r2), "=r"(r3) : "r"(addr));
}
__device__ __forceinline__ void ldsm4t(uint32_t& r0, uint32_t& r1, uint32_t& r2,
                                       uint32_t& r3, uint32_t addr) {
    asm volatile("ldmatrix.sync.aligned.m8n8.x4.trans.shared.b16 {%0,%1,%2,%3}, [%4];"
                 : "=r"(r0), "=r"(r1), "=r"(r2), "=r"(r3) : "r"(addr));
}
__device__ __forceinline__ void mma16816(float* c, const uint32_t* a, const uint32_t* b) {
    asm volatile(
        "mma.sync.aligned.m16n8k16.row.col.f32.bf16.bf16.f32 "
        "{%0,%1,%2,%3}, {%4,%5,%6,%7}, {%8,%9}, {%0,%1,%2,%3};"
        : "+f"(c[0]), "+f"(c[1]), "+f"(c[2]), "+f"(c[3])
        : "r"(a[0]), "r"(a[1]), "r"(a[2]), "r"(a[3]), "r"(b[0]), "r"(b[1]));
}
__device__ __forceinline__ uint32_t pack_bf16x2(float lo, float hi) {
    __nv_bfloat162 t = __floats2bfloat162_rn(lo, hi);
    return *reinterpret_cast<uint32_t*>(&t);
}
__device__ __forceinline__ float gelu_exact(float v) {
    return 0.5f * v * (1.f + erff(v * 0.70710678118654752f));
}

// ---------------- init ------------------------------------------------------
__global__ void init_kernel() {
    int t = threadIdx.x;
    if (t < NEXP) { g_count[t] = 0; g_cursor[t] = 0; g_imp[t] = 0.f; }
    if (t == 0)   g_ent = 0.f;
}

// ---------------- router (fp32) ---------------------------------------------
__global__ void router_kernel(const float* __restrict__ x,
                              const float* __restrict__ gW,
                              const float* __restrict__ gb) {
    int n    = blockIdx.x;
    int w    = threadIdx.x >> 5;
    int lane = threadIdx.x & 31;
    const float* xr = x + (size_t)n * DDIM;

    float s = 0.f;
    #pragma unroll 4
    for (int d = lane; d < DDIM; d += 32)
        s += xr[d] * gW[d * NEXP + w];
    #pragma unroll
    for (int o = 16; o; o >>= 1) s += __shfl_xor_sync(0xffffffffu, s, o);

    __shared__ float lg[NEXP];
    if (lane == 0) lg[w] = s + gb[w];
    __syncthreads();

    if (threadIdx.x == 0) {
        float l[NEXP];
        #pragma unroll
        for (int e = 0; e < NEXP; e++) l[e] = lg[e];
        int i1 = 0;
        #pragma unroll
        for (int e = 1; e < NEXP; e++) if (l[e] > l[i1]) i1 = e;
        int i2 = -1;
        #pragma unroll
        for (int e = 0; e < NEXP; e++)
            if (e != i1 && (i2 < 0 || l[e] > l[i2])) i2 = e;
        float v1 = l[i1], v2 = l[i2];
        float e2 = expf(v2 - v1);
        float p1 = 1.f / (1.f + e2);
        float p2 = e2 * p1;
        g_slotE[2*n] = i1;  g_slotE[2*n+1] = i2;
        g_slotW[2*n] = p1;  g_slotW[2*n+1] = p2;
        atomicAdd(&g_count[i1], 1);
        atomicAdd(&g_count[i2], 1);
        float p[NEXP], sum = 0.f;
        #pragma unroll
        for (int e = 0; e < NEXP; e++) { p[e] = expf(l[e] - v1); sum += p[e]; }
        float inv = 1.f / sum, ent = 0.f;
        #pragma unroll
        for (int e = 0; e < NEXP; e++) {
            p[e] *= inv;
            atomicAdd(&g_imp[e], p[e]);
            ent -= p[e] * logf(p[e] + 1e-8f);
        }
        atomicAdd(&g_ent, ent);
    }
}

// ---------------- offsets ---------------------------------------------------
__global__ void offsets_kernel() {
    if (threadIdx.x == 0 && blockIdx.x == 0) {
        int off = 0;
        for (int e = 0; e < NEXP; e++) {
            g_off[e] = off;
            int pc = (g_count[e] + TILE_M - 1) & ~(TILE_M - 1);
            int t0 = off >> 7, t1 = (off + pc) >> 7;
            for (int t = t0; t < t1; t++) g_tileExpert[t] = e;
            off += pc;
        }
        g_off[NEXP] = off;
        for (int t = off >> 7; t < MTILES; t++) g_tileExpert[t] = -1;
    }
}

// ---------------- gather: fp32 -> bf16 rows ---------------------------------
__global__ void gather_kernel(const float* __restrict__ x) {
    int n = blockIdx.x;
    __shared__ int pos[2];
    if (threadIdx.x == 0) {
        int e0 = g_slotE[2*n], e1 = g_slotE[2*n+1];
        pos[0] = g_off[e0] + atomicAdd(&g_cursor[e0], 1);
        pos[1] = g_off[e1] + atomicAdd(&g_cursor[e1], 1);
        g_slotPos[2*n] = pos[0]; g_slotPos[2*n+1] = pos[1];
    }
    __syncthreads();
    const float4* xr = (const float4*)(x + (size_t)n * DDIM);
    int i = threadIdx.x;
    float4 v = xr[i];
    uint2 u;
    u.x = pack_bf16x2(v.x, v.y);
    u.y = pack_bf16x2(v.z, v.w);
    ((uint2*)(g_Xg + (size_t)pos[0] * DDIM))[i] = u;
    ((uint2*)(g_Xg + (size_t)pos[1] * DDIM))[i] = u;
}

// ---------------- zero padded rows ------------------------------------------
__global__ void padzero_kernel() {
    int b = blockIdx.x;
    int e = b >> 7, r = b & 127;
    int row = g_off[e] + g_count[e] + r;
    if (row < g_off[e + 1]) {
        uint2 z = make_uint2(0u, 0u);
        ((uint2*)(g_Xg + (size_t)row * DDIM))[threadIdx.x] = z;
    }
}

// ---------------- weight convert fp32 -> bf16 (layout preserved) ------------
template <int STAGE>
__global__ void convert_w(const float* __restrict__ W) {
    constexpr size_t TOT = (size_t)NEXP * DDIM * HDIM;
    __nv_bfloat16* Wc = (STAGE == 0) ? g_W1c : g_W2c;
    size_t i = ((size_t)blockIdx.x * blockDim.x + threadIdx.x) * 4;
    if (i < TOT) {
        float4 v = *(const float4*)(W + i);
        uint2 u;
        u.x = pack_bf16x2(v.x, v.y);
        u.y = pack_bf16x2(v.z, v.w);
        *(uint2*)(Wc + i) = u;
    }
}

// ---------------- mma.sync expert GEMM (128x256 tile, bf16 HMMA) ------------
// STAGE 0: g_Xg [M,1024] @ W1c[K][N] -> bias+gelu -> g_Hbf (bf16)
// STAGE 1: g_Hbf [M,2048] @ W2c[K][N] -> bias      -> g_Yg  (fp32)
// 8 warps (2M x 4N), warp tile 64x64, K-chunk 32, 3-stage cp.async pipeline.
// A smem: [128 m-rows][64B k + 16 pad]  (ROWA=80;  banks step 20 -> conflict-free)
// B smem: [32 k-rows][512B n + 16 pad]  (ROWBB=528; banks step 4 -> conflict-free)
// B loaded from K-major weights via ldmatrix.x4.trans.
#define ROWA    80
#define ROWBB   528
#define A_BYTES (128 * ROWA)            // 10240
#define B_BYTES (32 * ROWBB)            // 16896
#define STAGEB  (A_BYTES + B_BYTES)     // 27136
#define NSTG    3
#define GEMM_SMEM (NSTG * STAGEB)       // 81408

template <int STAGE>
__global__ __launch_bounds__(256) void expert_gemm_mma(const float* __restrict__ bias)
{
    constexpr int K  = (STAGE == 0) ? DDIM : HDIM;
    constexpr int N  = (STAGE == 0) ? HDIM : DDIM;
    constexpr int NC = K / 32;
    const __nv_bfloat16* A  = (STAGE == 0) ? g_Xg  : g_Hbf;
    const __nv_bfloat16* Wc = (STAGE == 0) ? g_W1c : g_W2c;

    int e = g_tileExpert[blockIdx.x];
    if (e < 0) return;
    int m0 = blockIdx.x * TILE_M;
    int n0 = blockIdx.y * 256;

    extern __shared__ __align__(128) char sm[];
    uint32_t sbase = smem_to_u32(sm);

    int tid  = threadIdx.x;
    int wid  = tid >> 5, lane = tid & 31;
    int m_w  = (wid & 1) * 64;          // warp M offset
    int n_w  = (wid >> 1) * 64;         // warp N offset

    const __nv_bfloat16* Abase = A  + (size_t)m0 * K;
    const __nv_bfloat16* Bbase = Wc + (size_t)e * K * N + n0;   // rows = k

    // copy: A 512 cp16 (row=la>>2, q=la&3), B 1024 cp16 (krow=lb>>5, q=lb&31)
    auto copy_chunk = [&](int kc, int st) {
        uint32_t sA = sbase + st * STAGEB;
        uint32_t sB = sA + A_BYTES;
        #pragma unroll
        for (int i = 0; i < 2; i++) {
            int la = tid + i * 256;
            int row = la >> 2, q = la & 3;
            cp16(sA + row * ROWA + q * 16,
                 (const char*)(Abase + (size_t)row * K + kc * 32) + q * 16);
        }
        #pragma unroll
        for (int i = 0; i < 4; i++) {
            int lb = tid + i * 256;
            int krow = lb >> 5, q = lb & 31;
            cp16(sB + krow * ROWBB + q * 16,
                 (const char*)(Bbase + (size_t)(kc * 32 + krow) * N) + q * 16);
        }
    };

    float acc[4][8][4];
    #pragma unroll
    for (int i = 0; i < 4; i++)
        #pragma unroll
        for (int j = 0; j < 8; j++)
            #pragma unroll
            for (int q = 0; q < 4; q++) acc[i][j][q] = 0.f;

    int lr = lane & 7, lg = lane >> 3;
    // A (non-trans): matrices {m0-7/k0-7, m8-15/k0-7, m0-7/k8-15, m8-15/k8-15}
    uint32_t aoff = (uint32_t)(m_w + lr + (lg & 1) * 8) * ROWA + (lg >> 1) * 16;
    // B (trans, [k][n]): row k = (g&1)*8 + r, col n = (g>>1)*8
    uint32_t boff = (uint32_t)((lg & 1) * 8 + lr) * ROWBB + (n_w + (lg >> 1) * 8) * 2;

    copy_chunk(0, 0); CP_COMMIT();
    copy_chunk(1, 1); CP_COMMIT();

    for (int kc = 0; kc < NC; kc++) {
        int st = kc % NSTG;
        CP_WAIT(1);
        __syncthreads();
        if (kc + 2 < NC) { copy_chunk(kc + 2, (kc + 2) % NSTG); CP_COMMIT(); }

        uint32_t sA = sbase + st * STAGEB;
        uint32_t sB = sA + A_BYTES;
        #pragma unroll
        for (int ks = 0; ks < 2; ks++) {
            uint32_t a[4][4], b[8][2];
            #pragma unroll
            for (int f = 0; f < 4; f++)
                ldsm4(a[f][0], a[f][1], a[f][2], a[f][3],
                      sA + aoff + f * (16 * ROWA) + ks * 32);
            #pragma unroll
            for (int fb = 0; fb < 4; fb++)
                ldsm4t(b[2*fb][0], b[2*fb][1], b[2*fb+1][0], b[2*fb+1][1],
                       sB + boff + ks * (16 * ROWBB) + fb * 32);
            #pragma unroll
            for (int mf = 0; mf < 4; mf++)
                #pragma unroll
                for (int nf = 0; nf < 8; nf++)
                    mma16816(acc[mf][nf], a[mf], b[nf]);
        }
    }

    // ---- epilogue: bias (+GELU), direct global stores ----
    float bv[8][2];
    #pragma unroll
    for (int nf = 0; nf < 8; nf++) {
        int c = n0 + n_w + nf * 8 + (lane & 3) * 2;
        bv[nf][0] = bias[(size_t)e * N + c];
        bv[nf][1] = bias[(size_t)e * N + c + 1];
    }
    #pragma unroll
    for (int mf = 0; mf < 4; mf++) {
        #pragma unroll
        for (int sub = 0; sub < 2; sub++) {
            int row = m0 + m_w + mf * 16 + (lane >> 2) + sub * 8;
            #pragma unroll
            for (int nf = 0; nf < 8; nf++) {
                int col = n0 + n_w + nf * 8 + (lane & 3) * 2;
                float v0 = acc[mf][nf][sub * 2]     + bv[nf][0];
                float v1 = acc[mf][nf][sub * 2 + 1] + bv[nf][1];
                if (STAGE == 0) {
                    *(uint32_t*)(g_Hbf + (size_t)row * N + col) =
                        pack_bf16x2(gelu_exact(v0), gelu_exact(v1));
                } else {
                    *(float2*)(g_Yg + (size_t)row * N + col) = make_float2(v0, v1);
                }
            }
        }
    }
}

// ---------------- combine: gates + residual + layernorm (fp32) --------------
__global__ __launch_bounds__(256) void combine_ln(
    const float* __restrict__ x,
    const float* __restrict__ gamma,
    const float* __restrict__ beta,
    float* __restrict__ out)
{
    int n   = blockIdx.x;
    int tid = threadIdx.x;
    int   p0 = g_slotPos[2*n], p1 = g_slotPos[2*n+1];
    float w0 = g_slotW[2*n],   w1 = g_slotW[2*n+1];

    const float4* xr = (const float4*)(x    + (size_t)n  * DDIM);
    const float4* y0 = (const float4*)(g_Yg + (size_t)p0 * DDIM);
    const float4* y1 = (const float4*)(g_Yg + (size_t)p1 * DDIM);

    float4 a = y0[tid], b = y1[tid], xv = xr[tid];
    float4 z;
    z.x = w0 * a.x + w1 * b.x + xv.x;
    z.y = w0 * a.y + w1 * b.y + xv.y;
    z.z = w0 * a.z + w1 * b.z + xv.z;
    z.w = w0 * a.w + w1 * b.w + xv.w;

    float s  = z.x + z.y + z.z + z.w;
    float sq = z.x * z.x + z.y * z.y + z.z * z.z + z.w * z.w;
    #pragma unroll
    for (int o = 16; o; o >>= 1) {
        s  += __shfl_xor_sync(0xffffffffu, s,  o);
        sq += __shfl_xor_sync(0xffffffffu, sq, o);
    }
    __shared__ float ws[8], wq[8];
    int wid = tid >> 5, lane = tid & 31;
    if (lane == 0) { ws[wid] = s; wq[wid] = sq; }
    __syncthreads();
    __shared__ float mu_s, inv_s;
    if (tid == 0) {
        float ts = 0.f, tq = 0.f;
        #pragma unroll
        for (int i = 0; i < 8; i++) { ts += ws[i]; tq += wq[i]; }
        float mu  = ts * (1.f / DDIM);
        float var = tq * (1.f / DDIM) - mu * mu;
        mu_s  = mu;
        inv_s = rsqrtf(var + LN_EPS);
    }
    __syncthreads();
    float mu = mu_s, inv = inv_s;

    float4 g  = ((const float4*)gamma)[tid];
    float4 be = ((const float4*)beta)[tid];
    float4 o4;
    o4.x = (z.x - mu) * inv * g.x + be.x;
    o4.y = (z.y - mu) * inv * g.y + be.y;
    o4.z = (z.z - mu) * inv * g.z + be.z;
    o4.w = (z.w - mu) * inv * g.w + be.w;
    ((float4*)out)[(size_t)n * (DDIM / 4) + tid] = o4;
}

// ---------------- finalize aux outputs --------------------------------------
__global__ void finalize_kernel(float* __restrict__ out, int out_size) {
    if (threadIdx.x == 0 && blockIdx.x == 0) {
        const size_t ND = (size_t)NTOK * DDIM;
        float invN = 1.f / (float)NTOK;
        float loadv[NEXP], impv[NEXP];
        float bal = 0.f, ue = 0.f;
        for (int e = 0; e < NEXP; e++) {
            loadv[e] = (float)g_count[e] * invN;
            impv[e]  = g_imp[e] * invN;
            bal += impv[e] * loadv[e];
            ue  -= loadv[e] * logf(loadv[e] + 1e-8f);
        }
        float vals[3 + 2 * NEXP];
        vals[0] = (float)NEXP * bal;
        vals[1] = g_ent * invN;
        vals[2] = ue;
        for (int e = 0; e < NEXP; e++) { vals[3 + e] = loadv[e]; vals[11 + e] = impv[e]; }
        for (int i = 0; i < 3 + 2 * NEXP; i++) {
            size_t idx = ND + (size_t)i;
            if (idx < (size_t)out_size) out[idx] = vals[i];
        }
    }
}

// ---------------- launcher --------------------------------------------------
extern "C" void kernel_launch(void* const* d_in, const int* in_sizes, int n_in,
                              void* d_out, int out_size) {
    const float* x     = (const float*)d_in[0];
    const float* gateW = (const float*)d_in[1];
    const float* gateB = (const float*)d_in[2];
    const float* W1    = (const float*)d_in[3];
    const float* b1    = (const float*)d_in[4];
    const float* W2    = (const float*)d_in[5];
    const float* b2    = (const float*)d_in[6];
    const float* lngam = (const float*)d_in[7];
    const float* lnbet = (const float*)d_in[8];
    float* out = (float*)d_out;

    cudaFuncSetAttribute(expert_gemm_mma<0>,
                         cudaFuncAttributeMaxDynamicSharedMemorySize, GEMM_SMEM);
    cudaFuncSetAttribute(expert_gemm_mma<1>,
                         cudaFuncAttributeMaxDynamicSharedMemorySize, GEMM_SMEM);

    const int CONV_BLK = 256;
    const size_t WTOT4 = (size_t)NEXP * DDIM * HDIM / 4;
    int conv_grid = (int)((WTOT4 + CONV_BLK - 1) / CONV_BLK);

    init_kernel<<<1, 32>>>();
    router_kernel<<<NTOK, 256>>>(x, gateW, gateB);
    offsets_kernel<<<1, 32>>>();
    gather_kernel<<<NTOK, 256>>>(x);
    padzero_kernel<<<NEXP * TILE_M, 256>>>();
    convert_w<0><<<conv_grid, CONV_BLK>>>(W1);
    convert_w<1><<<conv_grid, CONV_BLK>>>(W2);
    expert_gemm_mma<0><<<dim3(MTILES, HDIM / 256), 256, GEMM_SMEM>>>(b1);
    expert_gemm_mma<1><<<dim3(MTILES, DDIM / 256), 256, GEMM_SMEM>>>(b2);
    combine_ln<<<NTOK, 256>>>(x, lngam, lnbet, out);
    finalize_kernel<<<1, 32>>>(out, out_size);
}